// round 14
// baseline (speedup 1.0000x reference)
#include <cuda_runtime.h>
#include <cstdint>

#define BATCH 32
#define DIM   256
#define HW    56
#define SP    (HW*HW)        // 3136
#define PW    7
#define PP    49
#define DD    3
#define N1    8
#define N2    8
#define NWIN  64
#define HEADS 8
#define DH    32
#define INNER 256
#define QKV_N 768
#define M_TOTAL (BATCH*NWIN*PP)   // 100352

#define PADW 136   // 136 mod 32 == 8 -> fragment LDS bank = 8*tq + tg (bijective)

__device__ float    g_qkv[(size_t)M_TOTAL * QKV_N];    // ~308 MB
__device__ uint32_t g_att32[(size_t)M_TOTAL * INNER];  // tf32 bits, ~103 MB
__device__ uint32_t g_wqkv32[DIM * QKV_N];             // prepped tf32 weights
__device__ uint32_t g_wout32[INNER * DIM];

typedef unsigned long long u64;

__device__ __forceinline__ u64 pack_dup(float x) {
    u64 r; unsigned u = __float_as_uint(x);
    asm("mov.b64 %0, {%1, %1};" : "=l"(r) : "r"(u));
    return r;
}
__device__ __forceinline__ void fma2(u64& d, u64 a, u64 b) {
    asm("fma.rn.f32x2 %0, %1, %2, %0;" : "+l"(d) : "l"(a), "l"(b));
}
__device__ __forceinline__ void mul2(u64& d, u64 a, u64 b) {
    asm("mul.rn.f32x2 %0, %1, %2;" : "=l"(d) : "l"(a), "l"(b));
}
__device__ __forceinline__ float2 unpack2(u64 v) {
    unsigned lo, hi;
    asm("mov.b64 {%0, %1}, %2;" : "=r"(lo), "=r"(hi) : "l"(v));
    return make_float2(__uint_as_float(lo), __uint_as_float(hi));
}
__device__ __forceinline__ uint32_t f2tf32(float f) {
    uint32_t r; asm("cvt.rna.tf32.f32 %0, %1;" : "=r"(r) : "f"(f)); return r;
}
__device__ __forceinline__ void mma_tf32(float* d, const uint32_t* a, const uint32_t* b) {
    asm volatile(
        "mma.sync.aligned.m16n8k8.row.col.f32.tf32.tf32.f32 "
        "{%0,%1,%2,%3}, {%4,%5,%6,%7}, {%8,%9}, {%0,%1,%2,%3};"
        : "+f"(d[0]), "+f"(d[1]), "+f"(d[2]), "+f"(d[3])
        : "r"(a[0]), "r"(a[1]), "r"(a[2]), "r"(a[3]), "r"(b[0]), "r"(b[1]));
}

__device__ __forceinline__ int row_to_off(int r) {
    int bi  = r / (NWIN * PP);
    int rem = r % (NWIN * PP);
    int w   = rem / PP;
    int t   = rem % PP;
    int n1i = w / N2, n2i = w % N2;
    int py  = t / PW, px  = t % PW;
    int hh  = (n1i * PW + py + DD) % HW;
    int ww  = (n2i * PW + px + DD) % HW;
    return bi * DIM * SP + hh * HW + ww;
}

// ---------------------------------------------------------------------------
// Kernel 0: pre-convert weights to tf32 bits
// ---------------------------------------------------------------------------
__global__ void prep_w(const float* __restrict__ wqkv, const float* __restrict__ wout) {
    const int t1 = DIM * QKV_N;
    const int t2 = INNER * DIM;
    for (int i = blockIdx.x * blockDim.x + threadIdx.x; i < t1 + t2;
         i += gridDim.x * blockDim.x) {
        if (i < t1) g_wqkv32[i] = f2tf32(wqkv[i]);
        else        g_wout32[i - t1] = f2tf32(wout[i - t1]);
    }
}

// ---------------------------------------------------------------------------
// Kernel 1: qkv GEMM — tf32 mma.sync, 128x128 tile, 4 warps of 64x64,
// double-buffered, 2 CTAs/SM (unchanged from R12)
// ---------------------------------------------------------------------------
__global__ void __launch_bounds__(128, 2) qkv_gemm(const float* __restrict__ x) {
    __shared__ uint32_t As[2][16][PADW];
    __shared__ uint32_t Bs[2][16][PADW];

    const int m0  = blockIdx.y * 128;
    const int n0  = blockIdx.x * 128;
    const int tid = threadIdx.x;

    const int lane = tid & 31;
    const int wid  = tid >> 5;
    const int mb   = (wid & 1) * 64;
    const int nb   = (wid >> 1) * 64;
    const int tg   = lane >> 2;
    const int tq   = lane & 3;

    const float*    arow = x + row_to_off(m0 + tid);
    const uint32_t* brow = g_wqkv32 + n0 + tid;

    float d[4][8][4] = {};
    float    a_reg[16];
    uint32_t b_reg[16];

    #pragma unroll
    for (int i = 0; i < 16; i++) {
        a_reg[i] = arow[i * SP];
        b_reg[i] = brow[i * QKV_N];
    }
    #pragma unroll
    for (int i = 0; i < 16; i++) {
        As[0][i][tid] = f2tf32(a_reg[i]);
        Bs[0][i][tid] = b_reg[i];
    }
    __syncthreads();

    for (int c = 0; c < 16; c++) {
        const int cur = c & 1;
        if (c < 15) {
            const int kb = (c + 1) * 16;
            #pragma unroll
            for (int i = 0; i < 16; i++) {
                a_reg[i] = arow[(kb + i) * SP];
                b_reg[i] = brow[(kb + i) * QKV_N];
            }
        }
        #pragma unroll
        for (int s = 0; s < 2; s++) {
            uint32_t a[4][4], b[8][2];
            #pragma unroll
            for (int am = 0; am < 4; am++) {
                int r = mb + am * 16 + tg;
                a[am][0] = As[cur][s * 8 + tq][r];
                a[am][1] = As[cur][s * 8 + tq][r + 8];
                a[am][2] = As[cur][s * 8 + tq + 4][r];
                a[am][3] = As[cur][s * 8 + tq + 4][r + 8];
            }
            #pragma unroll
            for (int an = 0; an < 8; an++) {
                int cc = nb + an * 8 + tg;
                b[an][0] = Bs[cur][s * 8 + tq][cc];
                b[an][1] = Bs[cur][s * 8 + tq + 4][cc];
            }
            #pragma unroll
            for (int am = 0; am < 4; am++)
                #pragma unroll
                for (int an = 0; an < 8; an++)
                    mma_tf32(d[am][an], a[am], b[an]);
        }
        if (c < 15) {
            const int nxt = cur ^ 1;
            #pragma unroll
            for (int i = 0; i < 16; i++) {
                As[nxt][i][tid] = f2tf32(a_reg[i]);
                Bs[nxt][i][tid] = b_reg[i];
            }
        }
        __syncthreads();
    }

    #pragma unroll
    for (int am = 0; am < 4; am++) {
        size_t r0 = (size_t)(m0 + mb + am * 16 + tg) * QKV_N;
        size_t r1 = r0 + 8 * QKV_N;
        #pragma unroll
        for (int an = 0; an < 8; an++) {
            int c = n0 + nb + an * 8 + 2 * tq;
            *(float2*)&g_qkv[r0 + c] = make_float2(d[am][an][0], d[am][an][1]);
            *(float2*)&g_qkv[r1 + c] = make_float2(d[am][an][2], d[am][an][3]);
        }
    }
}

// ---------------------------------------------------------------------------
// Kernel 2: per (b, window, head) attention — 4x8 micro-tiles (half the LDS)
// ---------------------------------------------------------------------------
__global__ void __launch_bounds__(256) attn_kernel(const float* __restrict__ pos,
                                                   float* __restrict__ attn_out) {
    const int bid  = blockIdx.x;
    const int head = bid % HEADS;
    const int bw   = bid / HEADS;
    const int w    = bw % NWIN;
    const int bi   = bw / NWIN;
    const int tid  = threadIdx.x;

    __shared__ float qT[DH][56];
    __shared__ float kT[DH][56];
    __shared__ float v[PP][DH];
    __shared__ float dots[PP][56];
    __shared__ float poss[169];
    __shared__ float cpart[PP][7];
    __shared__ float rowm[PP], rowinv[PP];

    const float* base = g_qkv + (size_t)(bi * NWIN + w) * PP * QKV_N + head * DH;
    for (int idx = tid; idx < PP * 8; idx += 256) {
        int t = idx >> 3, c = idx & 7;
        const float* rowp = base + (size_t)t * QKV_N + c * 4;
        float4 qf = *(const float4*)(rowp);
        float4 kf = *(const float4*)(rowp + INNER);
        float4 vf = *(const float4*)(rowp + 2 * INNER);
        *(float4*)&v[t][c * 4] = vf;
        int d = c * 4;
        qT[d][t] = qf.x; qT[d + 1][t] = qf.y; qT[d + 2][t] = qf.z; qT[d + 3][t] = qf.w;
        kT[d][t] = kf.x; kT[d + 1][t] = kf.y; kT[d + 2][t] = kf.z; kT[d + 3][t] = kf.w;
    }
    if (tid < DH) {
        #pragma unroll
        for (int p = 49; p < 56; p++) { qT[tid][p] = 0.f; kT[tid][p] = 0.f; }
    }
    for (int idx = tid; idx < 169; idx += 256) poss[idx] = pos[idx];
    __syncthreads();

    const bool m_ul = (w >= NWIN - N2);
    const bool m_lr = (w >= NWIN - N1 - 1) && ((w - (NWIN - N1 - 1)) % N1 == 0);
    const float NEG = -1e30f;
    const float scale = 0.17677669529663687f;

    // Pass 1: dots 4x8 micro-tile per thread (13 i-chunks x 7 j-chunks = 91)
    if (tid < 91) {
        int ic = tid / 7, jc = tid % 7;
        int i0 = ic * 4, j0 = jc * 8;
        u64 acc2[4][4] = {};
        #pragma unroll
        for (int d = 0; d < DH; d++) {
            float4 qf = *(const float4*)&qT[d][i0];
            ulonglong2 k2a = *(const ulonglong2*)&kT[d][j0];
            ulonglong2 k2b = *(const ulonglong2*)&kT[d][j0 + 4];
            float qa[4] = {qf.x, qf.y, qf.z, qf.w};
            #pragma unroll
            for (int ii = 0; ii < 4; ii++) {
                u64 q2 = pack_dup(qa[ii]);
                fma2(acc2[ii][0], q2, k2a.x);
                fma2(acc2[ii][1], q2, k2a.y);
                fma2(acc2[ii][2], q2, k2b.x);
                fma2(acc2[ii][3], q2, k2b.y);
            }
        }
        #pragma unroll
        for (int ii = 0; ii < 4; ii++) {
            int i = i0 + ii;
            if (i < PP) {
                float sv[8];
                #pragma unroll
                for (int p = 0; p < 4; p++) {
                    float2 pr = unpack2(acc2[ii][p]);
                    sv[2 * p] = pr.x; sv[2 * p + 1] = pr.y;
                }
                int iy = i / PW, ix = i % PW;
                float outv[8];
                float cm = -3.4e38f;
                #pragma unroll
                for (int jj = 0; jj < 8; jj++) {
                    int j = j0 + jj;
                    float val = NEG;
                    if (j < PP) {
                        int jy = j / PW, jx = j % PW;
                        val = sv[jj] * scale + poss[(jy - iy + 6) * 13 + (jx - ix + 6)];
                        if (m_ul && ((iy >= 4) != (jy >= 4))) val = NEG;
                        if (m_lr && ((ix >= 4) != (jx >= 4))) val = NEG;
                        cm = fmaxf(cm, val);
                    }
                    outv[jj] = val;
                }
                *(float4*)&dots[i][j0]     = make_float4(outv[0], outv[1], outv[2], outv[3]);
                *(float4*)&dots[i][j0 + 4] = make_float4(outv[4], outv[5], outv[6], outv[7]);
                cpart[i][jc] = cm;
            }
        }
    }
    __syncthreads();

    if (tid < PP) {
        float m = cpart[tid][0];
        #pragma unroll
        for (int c = 1; c < 7; c++) m = fmaxf(m, cpart[tid][c]);
        rowm[tid] = m;
    }
    __syncthreads();

    // Pass 2: exp + per-chunk sum (49 x 7 chunks of 8)
    for (int idx = tid; idx < PP * 7; idx += 256) {
        int i = idx / 7, jc = idx % 7, j0 = jc * 8;
        float m = rowm[i];
        float4 d0 = *(const float4*)&dots[i][j0];
        float4 d1 = *(const float4*)&dots[i][j0 + 4];
        float xv[8] = {d0.x, d0.y, d0.z, d0.w, d1.x, d1.y, d1.z, d1.w};
        float ev[8];
        float ps = 0.f;
        #pragma unroll
        for (int jj = 0; jj < 8; jj++) {
            float e = (j0 + jj < PP) ? __expf(xv[jj] - m) : 0.f;
            ev[jj] = e;
            ps += e;
        }
        *(float4*)&dots[i][j0]     = make_float4(ev[0], ev[1], ev[2], ev[3]);
        *(float4*)&dots[i][j0 + 4] = make_float4(ev[4], ev[5], ev[6], ev[7]);
        cpart[i][jc] = ps;
    }
    __syncthreads();

    if (tid < PP) {
        float s = 0.f;
        #pragma unroll
        for (int c = 0; c < 7; c++) s += cpart[tid][c];
        rowinv[tid] = 1.0f / s;
    }
    __syncthreads();

    // Overlapped final phase:
    //   threads 0..51   : attn @ v, 4x8 micro-tile over (i, d)
    //   threads 52..255 : normalized attn tensor write
    if (tid < 52) {
        int ic = tid >> 2, dc = tid & 3;
        int i0 = ic * 4, d0 = dc * 8;
        uint32_t* ob = g_att32 + (size_t)(bi * NWIN + w) * PP * INNER + head * DH;
        u64 acc2[4][4] = {};
        #pragma unroll
        for (int j = 0; j < PP; j++) {
            ulonglong2 v2a = *(const ulonglong2*)&v[j][d0];
            ulonglong2 v2b = *(const ulonglong2*)&v[j][d0 + 4];
            #pragma unroll
            for (int ii = 0; ii < 4; ii++) {
                u64 p2 = pack_dup(dots[i0 + ii][j]);
                fma2(acc2[ii][0], p2, v2a.x);
                fma2(acc2[ii][1], p2, v2a.y);
                fma2(acc2[ii][2], p2, v2b.x);
                fma2(acc2[ii][3], p2, v2b.y);
            }
        }
        #pragma unroll
        for (int ii = 0; ii < 4; ii++) {
            int i = i0 + ii;
            if (i < PP) {
                u64 r2 = pack_dup(rowinv[i]);
                uint4 uo0, uo1;
                u64 o;
                float2 p;
                mul2(o, acc2[ii][0], r2); p = unpack2(o); uo0.x = f2tf32(p.x); uo0.y = f2tf32(p.y);
                mul2(o, acc2[ii][1], r2); p = unpack2(o); uo0.z = f2tf32(p.x); uo0.w = f2tf32(p.y);
                mul2(o, acc2[ii][2], r2); p = unpack2(o); uo1.x = f2tf32(p.x); uo1.y = f2tf32(p.y);
                mul2(o, acc2[ii][3], r2); p = unpack2(o); uo1.z = f2tf32(p.x); uo1.w = f2tf32(p.y);
                *(uint4*)&ob[(size_t)i * INNER + d0]     = uo0;
                *(uint4*)&ob[(size_t)i * INNER + d0 + 4] = uo1;
            }
        }
    } else {
        float* ao = attn_out + (size_t)bid * (PP * PP);
        for (int idx = tid - 52; idx < PP * PP; idx += 204) {
            int i = idx / PP, j = idx % PP;
            ao[idx] = dots[i][j] * rowinv[i];
        }
    }
}

// ---------------------------------------------------------------------------
// Kernel 3: out = g_att @ w_out + b_out — 4 warps of 64x64, double-buffered,
// epilogue staged in two column-half passes (keeps smem small -> 2 CTAs/SM)
// ---------------------------------------------------------------------------
__global__ void __launch_bounds__(128, 2) out_gemm(const float* __restrict__ bout,
                                                   float* __restrict__ out) {
    __shared__ union U {
        struct { uint32_t As[2][16][PADW]; uint32_t Bs[2][16][PADW]; } mm;
        float sbuf[128][65];   // 33.3 KB <= mm size (34.8 KB)
        __device__ U() {}
    } sh;
    __shared__ int   rowoff[128];
    __shared__ float bout_s[128];

    const int m0  = blockIdx.y * 128;
    const int n0  = blockIdx.x * 128;
    const int tid = threadIdx.x;

    rowoff[tid] = row_to_off(m0 + tid);
    bout_s[tid] = bout[n0 + tid];

    const int lane = tid & 31;
    const int wid  = tid >> 5;
    const int mb   = (wid & 1) * 64;
    const int half_of_warp = wid >> 1;   // warp's column half (0 or 1)
    const int tg   = lane >> 2;
    const int tq   = lane & 3;

    const uint32_t* arow = g_att32 + (size_t)(m0 + tid) * INNER;
    const uint32_t* brow = g_wout32 + n0 + tid;

    float d[4][8][4] = {};
    uint32_t a_reg[16], b_reg[16];

    #pragma unroll
    for (int i = 0; i < 4; i++)
        *(uint4*)&a_reg[4 * i] = *(const uint4*)(arow + 4 * i);
    #pragma unroll
    for (int i = 0; i < 16; i++) b_reg[i] = brow[i * DIM];
    #pragma unroll
    for (int i = 0; i < 16; i++) {
        sh.mm.As[0][i][tid] = a_reg[i];
        sh.mm.Bs[0][i][tid] = b_reg[i];
    }
    __syncthreads();

    for (int c = 0; c < 16; c++) {
        const int cur = c & 1;
        if (c < 15) {
            const int kb = (c + 1) * 16;
            #pragma unroll
            for (int i = 0; i < 4; i++)
                *(uint4*)&a_reg[4 * i] = *(const uint4*)(arow + kb + 4 * i);
            #pragma unroll
            for (int i = 0; i < 16; i++) b_reg[i] = brow[(kb + i) * DIM];
        }
        #pragma unroll
        for (int s = 0; s < 2; s++) {
            uint32_t a[4][4], b[8][2];
            #pragma unroll
            for (int am = 0; am < 4; am++) {
                int r = mb + am * 16 + tg;
                a[am][0] = sh.mm.As[cur][s * 8 + tq][r];
                a[am][1] = sh.mm.As[cur][s * 8 + tq][r + 8];
                a[am][2] = sh.mm.As[cur][s * 8 + tq + 4][r];
                a[am][3] = sh.mm.As[cur][s * 8 + tq + 4][r + 8];
            }
            #pragma unroll
            for (int an = 0; an < 8; an++) {
                int cc = half_of_warp * 64 + an * 8 + tg;
                b[an][0] = sh.mm.Bs[cur][s * 8 + tq][cc];
                b[an][1] = sh.mm.Bs[cur][s * 8 + tq + 4][cc];
            }
            #pragma unroll
            for (int am = 0; am < 4; am++)
                #pragma unroll
                for (int an = 0; an < 8; an++)
                    mma_tf32(d[am][an], a[am], b[an]);
        }
        if (c < 15) {
            const int nxt = cur ^ 1;
            #pragma unroll
            for (int i = 0; i < 16; i++) {
                sh.mm.As[nxt][i][tid] = a_reg[i];
                sh.mm.Bs[nxt][i][tid] = b_reg[i];
            }
        }
        __syncthreads();
    }

    // Epilogue: two half-passes through a 128x65 staging buffer
    #pragma unroll
    for (int half = 0; half < 2; half++) {
        if (half_of_warp == half) {
            #pragma unroll
            for (int am = 0; am < 4; am++) {
                int r0 = mb + am * 16 + tg;
                #pragma unroll
                for (int an = 0; an < 8; an++) {
                    int c = an * 8 + 2 * tq;
                    sh.sbuf[r0][c]         = d[am][an][0];
                    sh.sbuf[r0][c + 1]     = d[am][an][1];
                    sh.sbuf[r0 + 8][c]     = d[am][an][2];
                    sh.sbuf[r0 + 8][c + 1] = d[am][an][3];
                }
            }
        }
        __syncthreads();
        #pragma unroll
        for (int it = 0; it < 64; it++) {
            int flat = it * 128 + tid;
            int m = flat & 127;
            int c = flat >> 7;           // 0..63
            int col = half * 64 + c;
            out[rowoff[m] + (n0 + col) * SP] = sh.sbuf[m][c] + bout_s[col];
        }
        __syncthreads();
    }
}

// ---------------------------------------------------------------------------
extern "C" void kernel_launch(void* const* d_in, const int* in_sizes, int n_in,
                              void* d_out, int out_size) {
    const float* x    = (const float*)d_in[0];
    const float* pos  = (const float*)d_in[1];
    const float* wqkv = (const float*)d_in[2];
    const float* wout = (const float*)d_in[3];
    const float* bout = (const float*)d_in[4];

    float* out      = (float*)d_out;
    float* attn_out = out + (size_t)BATCH * DIM * SP;

    prep_w<<<256, 256>>>(wqkv, wout);

    dim3 g1(QKV_N / 128, M_TOTAL / 128);
    qkv_gemm<<<g1, 128>>>(x);

    attn_kernel<<<BATCH * NWIN * HEADS, 256>>>(pos, attn_out);

    dim3 g3(DIM / 128, M_TOTAL / 128);
    out_gemm<<<g3, 128>>>(bout, out);
}

// round 15
// speedup vs baseline: 1.2707x; 1.2707x over previous
#include <cuda_runtime.h>
#include <cstdint>

#define BATCH 32
#define DIM   256
#define HW    56
#define SP    (HW*HW)
#define PW    7
#define PP    49
#define DD    3
#define N1    8
#define N2    8
#define NWIN  64
#define HEADS 8
#define DH    32
#define INNER 256
#define QKV_N 768
#define M_TOTAL (BATCH*NWIN*PP)

#define PADW 136

__device__ float    g_qkv[(size_t)M_TOTAL * QKV_N];
__device__ uint32_t g_att32[(size_t)M_TOTAL * INNER];
__device__ uint32_t g_wqkv32[DIM * QKV_N];
__device__ uint32_t g_wout32[INNER * DIM];

typedef unsigned long long u64;

__device__ __forceinline__ uint32_t f2tf32(float f) {
    uint32_t r; asm("cvt.rna.tf32.f32 %0, %1;" : "=r"(r) : "f"(f)); return r;
}
__device__ __forceinline__ void mma_tf32(float* d, const uint32_t* a, const uint32_t* b) {
    asm volatile(
        "mma.sync.aligned.m16n8k8.row.col.f32.tf32.tf32.f32 "
        "{%0,%1,%2,%3}, {%4,%5,%6,%7}, {%8,%9}, {%0,%1,%2,%3};"
        : "+f"(d[0]), "+f"(d[1]), "+f"(d[2]), "+f"(d[3])
        : "r"(a[0]), "r"(a[1]), "r"(a[2]), "r"(a[3]), "r"(b[0]), "r"(b[1]));
}

__device__ __forceinline__ int row_to_off(int r) {
    int bi  = r / (NWIN * PP);
    int rem = r % (NWIN * PP);
    int w   = rem / PP;
    int t   = rem % PP;
    int n1i = w / N2, n2i = w % N2;
    int py  = t / PW, px  = t % PW;
    int hh  = (n1i * PW + py + DD) % HW;
    int ww  = (n2i * PW + px + DD) % HW;
    return bi * DIM * SP + hh * HW + ww;
}

// ---------------------------------------------------------------------------
__global__ void prep_w(const float* __restrict__ wqkv, const float* __restrict__ wout) {
    const int t1 = DIM * QKV_N;
    const int t2 = INNER * DIM;
    for (int i = blockIdx.x * blockDim.x + threadIdx.x; i < t1 + t2;
         i += gridDim.x * blockDim.x) {
        if (i < t1) g_wqkv32[i] = f2tf32(wqkv[i]);
        else        g_wout32[i - t1] = f2tf32(wout[i - t1]);
    }
}

// ---------------------------------------------------------------------------
// Kernel 1: qkv GEMM (unchanged, measured)
// ---------------------------------------------------------------------------
__global__ void __launch_bounds__(128, 2) qkv_gemm(const float* __restrict__ x) {
    __shared__ uint32_t As[2][16][PADW];
    __shared__ uint32_t Bs[2][16][PADW];

    const int m0  = blockIdx.y * 128;
    const int n0  = blockIdx.x * 128;
    const int tid = threadIdx.x;

    const int lane = tid & 31;
    const int wid  = tid >> 5;
    const int mb   = (wid & 1) * 64;
    const int nb   = (wid >> 1) * 64;
    const int tg   = lane >> 2;
    const int tq   = lane & 3;

    const float*    arow = x + row_to_off(m0 + tid);
    const uint32_t* brow = g_wqkv32 + n0 + tid;

    float d[4][8][4] = {};
    float    a_reg[16];
    uint32_t b_reg[16];

    #pragma unroll
    for (int i = 0; i < 16; i++) {
        a_reg[i] = arow[i * SP];
        b_reg[i] = brow[i * QKV_N];
    }
    #pragma unroll
    for (int i = 0; i < 16; i++) {
        As[0][i][tid] = f2tf32(a_reg[i]);
        Bs[0][i][tid] = b_reg[i];
    }
    __syncthreads();

    for (int c = 0; c < 16; c++) {
        const int cur = c & 1;
        if (c < 15) {
            const int kb = (c + 1) * 16;
            #pragma unroll
            for (int i = 0; i < 16; i++) {
                a_reg[i] = arow[(kb + i) * SP];
                b_reg[i] = brow[(kb + i) * QKV_N];
            }
        }
        #pragma unroll
        for (int s = 0; s < 2; s++) {
            uint32_t a[4][4], b[8][2];
            #pragma unroll
            for (int am = 0; am < 4; am++) {
                int r = mb + am * 16 + tg;
                a[am][0] = As[cur][s * 8 + tq][r];
                a[am][1] = As[cur][s * 8 + tq][r + 8];
                a[am][2] = As[cur][s * 8 + tq + 4][r];
                a[am][3] = As[cur][s * 8 + tq + 4][r + 8];
            }
            #pragma unroll
            for (int an = 0; an < 8; an++) {
                int cc = nb + an * 8 + tg;
                b[an][0] = Bs[cur][s * 8 + tq][cc];
                b[an][1] = Bs[cur][s * 8 + tq + 4][cc];
            }
            #pragma unroll
            for (int am = 0; am < 4; am++)
                #pragma unroll
                for (int an = 0; an < 8; an++)
                    mma_tf32(d[am][an], a[am], b[an]);
        }
        if (c < 15) {
            const int nxt = cur ^ 1;
            #pragma unroll
            for (int i = 0; i < 16; i++) {
                As[nxt][i][tid] = f2tf32(a_reg[i]);
                Bs[nxt][i][tid] = b_reg[i];
            }
        }
        __syncthreads();
    }

    #pragma unroll
    for (int am = 0; am < 4; am++) {
        size_t r0 = (size_t)(m0 + mb + am * 16 + tg) * QKV_N;
        size_t r1 = r0 + 8 * QKV_N;
        #pragma unroll
        for (int an = 0; an < 8; an++) {
            int c = n0 + nb + an * 8 + 2 * tq;
            *(float2*)&g_qkv[r0 + c] = make_float2(d[am][an][0], d[am][an][1]);
            *(float2*)&g_qkv[r1 + c] = make_float2(d[am][an][2], d[am][an][3]);
        }
    }
}

// ---------------------------------------------------------------------------
// Kernel 2: attention via tensor cores.
// QK: D[i][j] = sum_d Q[i,d]K[j,d]  — A=qT[d][i] (k-major), B=kT[d][j]
// AV: O[i][d] = sum_j P[i,j]V[j,d]  — A=dotsT[j][i], B=v[j][d]
// Pads: addr mod 32 bijective over (tg,tq) for every fragment access.
// ---------------------------------------------------------------------------
__global__ void __launch_bounds__(256) attn_kernel(const float* __restrict__ pos,
                                                   float* __restrict__ attn_out) {
    const int bid  = blockIdx.x;
    const int head = bid % HEADS;
    const int bw   = bid / HEADS;
    const int w    = bw % NWIN;
    const int bi   = bw / NWIN;
    const int tid  = threadIdx.x;
    const int lane = tid & 31;
    const int wid  = tid >> 5;
    const int tg   = lane >> 2;
    const int tq   = lane & 3;

    __shared__ uint32_t qT[DH][72];     // tf32 bits, 72 % 32 == 8
    __shared__ uint32_t kT[DH][56];     // 56 % 32 == 24 (== -8)
    __shared__ uint32_t v[56][40];      // 40 % 32 == 8 ; rows 49-55 zeroed
    __shared__ uint32_t dotsT[56][72];  // [j][i]; rows 49-55 zeroed
    __shared__ float poss[169];
    __shared__ float cpart[PP][7];
    __shared__ float rowinv[PP];

    const float* base = g_qkv + (size_t)(bi * NWIN + w) * PP * QKV_N + head * DH;
    for (int idx = tid; idx < PP * 8; idx += 256) {
        int t = idx >> 3, c = idx & 7;
        const float* rowp = base + (size_t)t * QKV_N + c * 4;
        float4 qf = *(const float4*)(rowp);
        float4 kf = *(const float4*)(rowp + INNER);
        float4 vf = *(const float4*)(rowp + 2 * INNER);
        int d = c * 4;
        qT[d][t] = f2tf32(qf.x); qT[d + 1][t] = f2tf32(qf.y);
        qT[d + 2][t] = f2tf32(qf.z); qT[d + 3][t] = f2tf32(qf.w);
        kT[d][t] = f2tf32(kf.x); kT[d + 1][t] = f2tf32(kf.y);
        kT[d + 2][t] = f2tf32(kf.z); kT[d + 3][t] = f2tf32(kf.w);
        v[t][d]     = f2tf32(vf.x); v[t][d + 1] = f2tf32(vf.y);
        v[t][d + 2] = f2tf32(vf.z); v[t][d + 3] = f2tf32(vf.w);
    }
    for (int idx = tid; idx < 7 * 40; idx += 256)  v[49 + idx / 40][idx % 40] = 0u;
    for (int idx = tid; idx < 7 * 72; idx += 256)  dotsT[49 + idx / 72][idx % 72] = 0u;
    for (int idx = tid; idx < 169; idx += 256)     poss[idx] = pos[idx];
    __syncthreads();

    const bool m_ul = (w >= NWIN - N2);
    const bool m_lr = (w >= NWIN - N1 - 1) && ((w - (NWIN - N1 - 1)) % N1 == 0);
    const float NEG = -1e30f;
    const float scale = 0.17677669529663687f;

    // ---- QK: warps 0-6, warp = n-atom (8 j-cols), 4 m-atoms, 4 k-steps ----
    if (wid < 7) {
        const int na = wid;
        const int j0 = na * 8 + 2 * tq;
        float dreg[4][4] = {};
        #pragma unroll
        for (int s = 0; s < 4; s++) {
            uint32_t b[2];
            b[0] = kT[s * 8 + tq][na * 8 + tg];
            b[1] = kT[s * 8 + tq + 4][na * 8 + tg];
            #pragma unroll
            for (int ma = 0; ma < 4; ma++) {
                int r = ma * 16 + tg;
                uint32_t a[4];
                a[0] = qT[s * 8 + tq][r];
                a[1] = qT[s * 8 + tq][r + 8];
                a[2] = qT[s * 8 + tq + 4][r];
                a[3] = qT[s * 8 + tq + 4][r + 8];
                mma_tf32(dreg[ma], a, b);
            }
        }
        // epilogue: bias + masks + transposed store + per-row chunk max
        #pragma unroll
        for (int ma = 0; ma < 4; ma++) {
            int r0 = ma * 16 + tg;
            int r1 = r0 + 8;
            float vals[2][2] = {{dreg[ma][0], dreg[ma][1]}, {dreg[ma][2], dreg[ma][3]}};
            float rmax[2];
            #pragma unroll
            for (int h = 0; h < 2; h++) {
                int i = h ? r1 : r0;
                float cm = NEG;
                if (i < PP) {
                    int iy = i / PW, ix = i % PW;
                    #pragma unroll
                    for (int jj = 0; jj < 2; jj++) {
                        int j = j0 + jj;
                        float val = NEG;
                        if (j < PP) {
                            int jy = j / PW, jx = j % PW;
                            val = vals[h][jj] * scale + poss[(jy - iy + 6) * 13 + (jx - ix + 6)];
                            if (m_ul && ((iy >= 4) != (jy >= 4))) val = NEG;
                            if (m_lr && ((ix >= 4) != (jx >= 4))) val = NEG;
                            dotsT[j][i] = __float_as_uint(val);
                            cm = fmaxf(cm, val);
                        }
                    }
                }
                rmax[h] = cm;
            }
            // reduce max over the tq quad (lanes differing in bits 0,1)
            #pragma unroll
            for (int h = 0; h < 2; h++) {
                rmax[h] = fmaxf(rmax[h], __shfl_xor_sync(0xffffffffu, rmax[h], 1));
                rmax[h] = fmaxf(rmax[h], __shfl_xor_sync(0xffffffffu, rmax[h], 2));
            }
            if (tq == 0) {
                if (r0 < PP) cpart[r0][na] = rmax[0];
                if (r1 < PP) cpart[r1][na] = rmax[1];
            }
        }
    }
    __syncthreads();

    // ---- softmax: one thread per row ----
    if (tid < PP) {
        int i = tid;
        float mx = cpart[i][0];
        #pragma unroll
        for (int c = 1; c < 7; c++) mx = fmaxf(mx, cpart[i][c]);
        float s = 0.f;
        for (int j = 0; j < PP; j++) {
            float e = __expf(__uint_as_float(dotsT[j][i]) - mx);
            dotsT[j][i] = f2tf32(e);
            s += e;
        }
        rowinv[i] = 1.0f / s;
    }
    __syncthreads();

    // ---- AV: 8 warps, warp = (m-half, n-atom); 2 m-atoms x 7 k-steps ----
    {
        const int na = wid & 3;
        const int mh = wid >> 2;
        uint32_t* ob = g_att32 + (size_t)(bi * NWIN + w) * PP * INNER + head * DH;
        float dreg[2][4] = {};
        #pragma unroll
        for (int t = 0; t < 7; t++) {
            uint32_t b[2];
            b[0] = v[t * 8 + tq][na * 8 + tg];
            b[1] = v[t * 8 + tq + 4][na * 8 + tg];
            #pragma unroll
            for (int mi = 0; mi < 2; mi++) {
                int r = (mh * 2 + mi) * 16 + tg;
                uint32_t a[4];
                a[0] = dotsT[t * 8 + tq][r];
                a[1] = dotsT[t * 8 + tq][r + 8];
                a[2] = dotsT[t * 8 + tq + 4][r];
                a[3] = dotsT[t * 8 + tq + 4][r + 8];
                mma_tf32(dreg[mi], a, b);
            }
        }
        #pragma unroll
        for (int mi = 0; mi < 2; mi++) {
            int r0 = (mh * 2 + mi) * 16 + tg;
            int dcol = na * 8 + 2 * tq;
            if (r0 < PP) {
                float inv = rowinv[r0];
                uint2 o;
                o.x = f2tf32(dreg[mi][0] * inv);
                o.y = f2tf32(dreg[mi][1] * inv);
                *(uint2*)&ob[(size_t)r0 * INNER + dcol] = o;
            }
            int r1 = r0 + 8;
            if (r1 < PP) {
                float inv = rowinv[r1];
                uint2 o;
                o.x = f2tf32(dreg[mi][2] * inv);
                o.y = f2tf32(dreg[mi][3] * inv);
                *(uint2*)&ob[(size_t)r1 * INNER + dcol] = o;
            }
        }
    }

    // ---- attn tensor output (reads tf32-rounded probs) ----
    float* ao = attn_out + (size_t)bid * (PP * PP);
    for (int idx = tid; idx < PP * PP; idx += 256) {
        int i = idx / PP, j = idx % PP;
        ao[idx] = __uint_as_float(dotsT[j][i]) * rowinv[i];
    }
}

// ---------------------------------------------------------------------------
// Kernel 3: out GEMM (unchanged, measured 154 us)
// ---------------------------------------------------------------------------
__global__ void __launch_bounds__(128, 2) out_gemm(const float* __restrict__ bout,
                                                   float* __restrict__ out) {
    __shared__ union U {
        struct { uint32_t As[2][16][PADW]; uint32_t Bs[2][16][PADW]; } mm;
        float sbuf[128][65];
        __device__ U() {}
    } sh;
    __shared__ int   rowoff[128];
    __shared__ float bout_s[128];

    const int m0  = blockIdx.y * 128;
    const int n0  = blockIdx.x * 128;
    const int tid = threadIdx.x;

    rowoff[tid] = row_to_off(m0 + tid);
    bout_s[tid] = bout[n0 + tid];

    const int lane = tid & 31;
    const int wid  = tid >> 5;
    const int mb   = (wid & 1) * 64;
    const int half_of_warp = wid >> 1;
    const int tg   = lane >> 2;
    const int tq   = lane & 3;

    const uint32_t* arow = g_att32 + (size_t)(m0 + tid) * INNER;
    const uint32_t* brow = g_wout32 + n0 + tid;

    float d[4][8][4] = {};
    uint32_t a_reg[16], b_reg[16];

    #pragma unroll
    for (int i = 0; i < 4; i++)
        *(uint4*)&a_reg[4 * i] = *(const uint4*)(arow + 4 * i);
    #pragma unroll
    for (int i = 0; i < 16; i++) b_reg[i] = brow[i * DIM];
    #pragma unroll
    for (int i = 0; i < 16; i++) {
        sh.mm.As[0][i][tid] = a_reg[i];
        sh.mm.Bs[0][i][tid] = b_reg[i];
    }
    __syncthreads();

    for (int c = 0; c < 16; c++) {
        const int cur = c & 1;
        if (c < 15) {
            const int kb = (c + 1) * 16;
            #pragma unroll
            for (int i = 0; i < 4; i++)
                *(uint4*)&a_reg[4 * i] = *(const uint4*)(arow + kb + 4 * i);
            #pragma unroll
            for (int i = 0; i < 16; i++) b_reg[i] = brow[(kb + i) * DIM];
        }
        #pragma unroll
        for (int s = 0; s < 2; s++) {
            uint32_t a[4][4], b[8][2];
            #pragma unroll
            for (int am = 0; am < 4; am++) {
                int r = mb + am * 16 + tg;
                a[am][0] = sh.mm.As[cur][s * 8 + tq][r];
                a[am][1] = sh.mm.As[cur][s * 8 + tq][r + 8];
                a[am][2] = sh.mm.As[cur][s * 8 + tq + 4][r];
                a[am][3] = sh.mm.As[cur][s * 8 + tq + 4][r + 8];
            }
            #pragma unroll
            for (int an = 0; an < 8; an++) {
                int cc = half_of_warp * 64 + an * 8 + tg;
                b[an][0] = sh.mm.Bs[cur][s * 8 + tq][cc];
                b[an][1] = sh.mm.Bs[cur][s * 8 + tq + 4][cc];
            }
            #pragma unroll
            for (int am = 0; am < 4; am++)
                #pragma unroll
                for (int an = 0; an < 8; an++)
                    mma_tf32(d[am][an], a[am], b[an]);
        }
        if (c < 15) {
            const int nxt = cur ^ 1;
            #pragma unroll
            for (int i = 0; i < 16; i++) {
                sh.mm.As[nxt][i][tid] = a_reg[i];
                sh.mm.Bs[nxt][i][tid] = b_reg[i];
            }
        }
        __syncthreads();
    }

    #pragma unroll
    for (int half = 0; half < 2; half++) {
        if (half_of_warp == half) {
            #pragma unroll
            for (int am = 0; am < 4; am++) {
                int r0 = mb + am * 16 + tg;
                #pragma unroll
                for (int an = 0; an < 8; an++) {
                    int c = an * 8 + 2 * tq;
                    sh.sbuf[r0][c]         = d[am][an][0];
                    sh.sbuf[r0][c + 1]     = d[am][an][1];
                    sh.sbuf[r0 + 8][c]     = d[am][an][2];
                    sh.sbuf[r0 + 8][c + 1] = d[am][an][3];
                }
            }
        }
        __syncthreads();
        #pragma unroll
        for (int it = 0; it < 64; it++) {
            int flat = it * 128 + tid;
            int m = flat & 127;
            int c = flat >> 7;
            int col = half * 64 + c;
            out[rowoff[m] + (n0 + col) * SP] = sh.sbuf[m][c] + bout_s[col];
        }
        __syncthreads();
    }
}

// ---------------------------------------------------------------------------
extern "C" void kernel_launch(void* const* d_in, const int* in_sizes, int n_in,
                              void* d_out, int out_size) {
    const float* x    = (const float*)d_in[0];
    const float* pos  = (const float*)d_in[1];
    const float* wqkv = (const float*)d_in[2];
    const float* wout = (const float*)d_in[3];
    const float* bout = (const float*)d_in[4];

    float* out      = (float*)d_out;
    float* attn_out = out + (size_t)BATCH * DIM * SP;

    prep_w<<<256, 256>>>(wqkv, wout);

    dim3 g1(QKV_N / 128, M_TOTAL / 128);
    qkv_gemm<<<g1, 128>>>(x);

    attn_kernel<<<BATCH * NWIN * HEADS, 256>>>(pos, attn_out);

    dim3 g3(DIM / 128, M_TOTAL / 128);
    out_gemm<<<g3, 128>>>(bout, out);
}